// round 12
// baseline (speedup 1.0000x reference)
#include <cuda_runtime.h>
#include <cuda_bf16.h>
#include <math.h>

#define NLAYERS 40
#define TB 256
#define NT 256

// padded strides: stride(bytes) % 128 == 32 -> conflict-free 8B fragment loads
#define SA_STRIDE 288      // A rows: 256B data + 32 pad
#define SW1_STRIDE 288     // W1 rows: 256B data + 32 pad
#define SW2_STRIDE 160     // W2 rows: 128B data + 32 pad

// smem layout (bytes)
#define OFF_A_HI 0                  // 256*288 = 73728
#define OFF_A_LO 73728              // 73728
#define OFF_W    147456             // shared weight region, hi part (18432)
#define OFF_WLO  165888             // lo part (18432)
#define OFF_BIAS 184320             // 192 f32
#define SMEM_BYTES 185088

// ---------------- global scratch ----------------
__device__ float g_buf0[8 * 64 * 8192];
__device__ float g_buf1[8 * 64 * 8192];
__device__ __align__(16) unsigned char g_w1img[NLAYERS * 36864];  // [hi 18432][lo 18432], stride 288
__device__ __align__(16) unsigned char g_w2img[NLAYERS * 61440];  // [hi 30720][lo 30720], stride 160
__device__ float g_bias[NLAYERS * 192];

// ---------------- helpers ----------------
__device__ __forceinline__ void mma_bf16(float* c, const unsigned* a, const unsigned* b) {
    asm volatile(
        "mma.sync.aligned.m16n8k16.row.col.f32.bf16.bf16.f32 "
        "{%0,%1,%2,%3}, {%4,%5,%6,%7}, {%8,%9}, {%0,%1,%2,%3};"
        : "+f"(c[0]), "+f"(c[1]), "+f"(c[2]), "+f"(c[3])
        : "r"(a[0]), "r"(a[1]), "r"(a[2]), "r"(a[3]), "r"(b[0]), "r"(b[1]));
}

__device__ __forceinline__ void split2(float a, float b, unsigned& hi, unsigned& lo) {
    __nv_bfloat16 ha = __float2bfloat16(a), hb = __float2bfloat16(b);
    float la = a - __bfloat162float(ha);
    float lb = b - __bfloat162float(hb);
    hi = ((unsigned)__bfloat16_as_ushort(hb) << 16) | (unsigned)__bfloat16_as_ushort(ha);
    __nv_bfloat16 bla = __float2bfloat16(la), blb = __float2bfloat16(lb);
    lo = ((unsigned)__bfloat16_as_ushort(blb) << 16) | (unsigned)__bfloat16_as_ushort(bla);
}

__device__ __forceinline__ float gate_fn(float y) {
    float ay = fabsf(y);
    float e1 = __expf(-ay);
    float e2 = e1 * e1;
    float th = __fdividef(1.f - e2, 1.f + e2);
    float sp = __fdividef(1.f, 1.f + e1);
    float sig = (y >= 0.f) ? sp : (1.f - sp);
    return copysignf(th, y) * sig;
}

// word-pair interleave within a 32B K-chunk: element e (0..15, bf16) -> byte offset
__device__ __forceinline__ unsigned ilv(unsigned e) {
    unsigned w = e >> 1;
    unsigned nw = (w < 4) ? (w * 8) : ((w - 4) * 8 + 4);
    return nw + (e & 1) * 2;
}

// ------------------------- weight repack -------------------------
#define RN1 (NLAYERS * 64 * 64 * 2)
#define RN2 (NLAYERS * 64 * 64)
#define RN3 (NLAYERS * 128 * 64)
#define RN4 (NLAYERS * 64)
#define RN5 (NLAYERS * 128)
#define RNTOT (RN1 + RN2 + RN3 + RN4 + RN5)

__global__ void repack_kernel(const float* __restrict__ wd, const float* __restrict__ wr,
                              const float* __restrict__ br, const float* __restrict__ ws,
                              const float* __restrict__ bs) {
    int idx = blockIdx.x * blockDim.x + threadIdx.x;
    if (idx < RN1) {  // w_dil[l][o][i][k] -> W1 row o, col k*64+i
        float v = wd[idx];
        int k = idx & 1, i = (idx >> 1) & 63, o = (idx >> 7) & 63, l = idx >> 13;
        __nv_bfloat16 h = __float2bfloat16(v);
        __nv_bfloat16 lo = __float2bfloat16(v - __bfloat162float(h));
        unsigned col = (unsigned)(k * 64 + i);
        unsigned byte = (unsigned)o * SW1_STRIDE + (col >> 4) * 32 + ilv(col & 15);
        *(__nv_bfloat16*)(g_w1img + (size_t)l * 36864 + byte) = h;
        *(__nv_bfloat16*)(g_w1img + (size_t)l * 36864 + 18432 + byte) = lo;
        return;
    }
    idx -= RN1;
    if (idx < RN2) {  // w_res[l][o][i] -> W2 row o
        float v = wr[idx];
        int i = idx & 63, o = (idx >> 6) & 63, l = idx >> 12;
        __nv_bfloat16 h = __float2bfloat16(v);
        __nv_bfloat16 lo = __float2bfloat16(v - __bfloat162float(h));
        unsigned byte = (unsigned)o * SW2_STRIDE + ((unsigned)i >> 4) * 32 + ilv((unsigned)i & 15);
        *(__nv_bfloat16*)(g_w2img + (size_t)l * 61440 + byte) = h;
        *(__nv_bfloat16*)(g_w2img + (size_t)l * 61440 + 30720 + byte) = lo;
        return;
    }
    idx -= RN2;
    if (idx < RN3) {  // w_skip[l][o][i] -> W2 row 64+o
        float v = ws[idx];
        int i = idx & 63, o = (idx >> 6) & 127, l = idx >> 13;
        __nv_bfloat16 h = __float2bfloat16(v);
        __nv_bfloat16 lo = __float2bfloat16(v - __bfloat162float(h));
        unsigned byte = (unsigned)(64 + o) * SW2_STRIDE + ((unsigned)i >> 4) * 32 + ilv((unsigned)i & 15);
        *(__nv_bfloat16*)(g_w2img + (size_t)l * 61440 + byte) = h;
        *(__nv_bfloat16*)(g_w2img + (size_t)l * 61440 + 30720 + byte) = lo;
        return;
    }
    idx -= RN3;
    if (idx < RN4) { int o = idx & 63, l = idx >> 6; g_bias[l * 192 + o] = br[idx]; return; }
    idx -= RN4;
    if (idx < RN5) { int o = idx & 127, l = idx >> 7; g_bias[l * 192 + 64 + o] = bs[idx]; return; }
}

// ------------------------- fused mma.sync layer kernel -------------------------
// CTA: 256 timesteps x one batch. 8 warps; warp w owns rows 32w..32w+31 (2 m16 tiles).
__global__ __launch_bounds__(NT, 1) void layer_kernel(
    const float* __restrict__ src, float* __restrict__ dst,
    const unsigned char* __restrict__ w1img, const unsigned char* __restrict__ w2img,
    const float* __restrict__ bias, float* __restrict__ skipOut,
    int d, int L, int nTiles) {
    extern __shared__ unsigned char smem[];
    const int tid = threadIdx.x;
    const int lane = tid & 31;
    const int w = tid >> 5;
    const int b = blockIdx.y;
    const int t0 = L - (nTiles - blockIdx.x) * TB;
    const int Tin = L + d;

    // ---- stage W1 (hi+lo contiguous, 2304 uint4) + bias ----
    {
        const uint4* g1 = (const uint4*)w1img;
        uint4* s1 = (uint4*)(smem + OFF_W);
#pragma unroll
        for (int k = 0; k < 9; k++) s1[tid + NT * k] = g1[tid + NT * k];
        float* sBias = (float*)(smem + OFF_BIAS);
        if (tid < 192) sBias[tid] = bias[tid];
    }

    // ---- stage A: thread = row, loop taps. Coalesced gmem loads, bf16 hi/lo scatter ----
    const float* srcB = src + (size_t)b * 64 * 8192;
    {
        const int row = tid;
        unsigned rowb = (unsigned)row * SA_STRIDE;
#pragma unroll
        for (int tap = 0; tap < 2; tap++) {
            const int sh = tap ? d : 0;
            int g = t0 + row + sh;
            g = min(max(g, 0), Tin - 1);
            const float* colp = srcB + g;
#pragma unroll
            for (int cc = 0; cc < 4; cc++) {
                float v[16];
#pragma unroll
                for (int e = 0; e < 16; e++) v[e] = colp[(size_t)(cc * 16 + e) * 8192];
                unsigned addr0 = rowb + (unsigned)(tap * 4 + cc) * 32;
#pragma unroll
                for (int hh = 0; hh < 2; hh++) {
                    unsigned h[4], l[4];
                    split2(v[4 * hh + 0], v[4 * hh + 1], h[0], l[0]);
                    split2(v[4 * hh + 8], v[4 * hh + 9], h[1], l[1]);
                    split2(v[4 * hh + 2], v[4 * hh + 3], h[2], l[2]);
                    split2(v[4 * hh + 10], v[4 * hh + 11], h[3], l[3]);
                    unsigned a = addr0 + hh * 16;
                    *(uint4*)(smem + OFF_A_HI + a) = make_uint4(h[0], h[1], h[2], h[3]);
                    *(uint4*)(smem + OFF_A_LO + a) = make_uint4(l[0], l[1], l[2], l[3]);
                }
            }
        }
    }
    __syncthreads();

    const int tg = lane & 3;
    const int rfrag = lane >> 2;

    // ---------------- phase 1: y = A @ W1^T (3-split bf16, 2 m-tiles/warp) ----------------
    float acc[2][8][4];
#pragma unroll
    for (int mt = 0; mt < 2; mt++)
#pragma unroll
        for (int nn = 0; nn < 8; nn++)
#pragma unroll
            for (int q = 0; q < 4; q++) acc[mt][nn][q] = 0.f;

#pragma unroll 2
    for (int kk = 0; kk < 8; kk++) {
        unsigned ah[2][4], al[2][4];
#pragma unroll
        for (int mt = 0; mt < 2; mt++) {
            unsigned ra = (unsigned)(w * 32 + mt * 16 + rfrag) * SA_STRIDE + (unsigned)kk * 32 + (unsigned)tg * 8;
            uint2 uh = *(const uint2*)(smem + OFF_A_HI + ra);
            uint2 vh = *(const uint2*)(smem + OFF_A_HI + ra + 8 * SA_STRIDE);
            uint2 ul = *(const uint2*)(smem + OFF_A_LO + ra);
            uint2 vl = *(const uint2*)(smem + OFF_A_LO + ra + 8 * SA_STRIDE);
            ah[mt][0] = uh.x; ah[mt][1] = vh.x; ah[mt][2] = uh.y; ah[mt][3] = vh.y;
            al[mt][0] = ul.x; al[mt][1] = vl.x; al[mt][2] = ul.y; al[mt][3] = vl.y;
        }
#pragma unroll
        for (int nn = 0; nn < 8; nn++) {
            unsigned nb = (unsigned)(nn * 8 + rfrag) * SW1_STRIDE + (unsigned)kk * 32 + (unsigned)tg * 8;
            uint2 bhv = *(const uint2*)(smem + OFF_W + nb);
            uint2 blv = *(const uint2*)(smem + OFF_WLO + nb);
            unsigned bh[2] = {bhv.x, bhv.y};
            unsigned bl[2] = {blv.x, blv.y};
            mma_bf16(acc[0][nn], ah[0], bh);
            mma_bf16(acc[1][nn], ah[1], bh);
            mma_bf16(acc[0][nn], al[0], bh);
            mma_bf16(acc[1][nn], al[1], bh);
            mma_bf16(acc[0][nn], ah[0], bl);
            mma_bf16(acc[1][nn], ah[1], bl);
        }
    }

    // ---------------- gate -> phase2 A fragments (registers only) ----------------
    unsigned gh[2][4][4], gl[2][4][4];
#pragma unroll
    for (int mt = 0; mt < 2; mt++) {
#pragma unroll
        for (int kt = 0; kt < 4; kt++) {
            int n0 = 2 * kt, n1 = 2 * kt + 1;
            split2(gate_fn(acc[mt][n0][0]), gate_fn(acc[mt][n0][1]), gh[mt][kt][0], gl[mt][kt][0]);
            split2(gate_fn(acc[mt][n0][2]), gate_fn(acc[mt][n0][3]), gh[mt][kt][1], gl[mt][kt][1]);
            split2(gate_fn(acc[mt][n1][0]), gate_fn(acc[mt][n1][1]), gh[mt][kt][2], gl[mt][kt][2]);
            split2(gate_fn(acc[mt][n1][2]), gate_fn(acc[mt][n1][3]), gh[mt][kt][3], gl[mt][kt][3]);
        }
    }

    // ---------------- phase 2: [res | skip] = G @ W2^T, W2 staged per 64-ch chunk ----------------
    const int skipOff = L - 4096;
    const bool needSkip = (t0 + TB > skipOff);
    const int nch = needSkip ? 3 : 1;
    const float* sBias = (const float*)(smem + OFF_BIAS);

    for (int c = 0; c < nch; c++) {
        __syncthreads();   // everyone done reading the weight region
        {
            const uint4* ghi = (const uint4*)(w2img + (size_t)c * 10240);
            const uint4* glo = (const uint4*)(w2img + 30720 + (size_t)c * 10240);
            uint4* shi = (uint4*)(smem + OFF_W);
            uint4* slo = (uint4*)(smem + OFF_WLO);
#pragma unroll
            for (int k = 0; k < 3; k++) {
                int i = tid + NT * k;
                if (i < 640) { shi[i] = ghi[i]; slo[i] = glo[i]; }
            }
        }
        __syncthreads();

        float acc2[2][8][4];
#pragma unroll
        for (int mt = 0; mt < 2; mt++)
#pragma unroll
            for (int nn = 0; nn < 8; nn++)
#pragma unroll
                for (int q = 0; q < 4; q++) acc2[mt][nn][q] = 0.f;

#pragma unroll
        for (int kt = 0; kt < 4; kt++) {
#pragma unroll
            for (int nn = 0; nn < 8; nn++) {
                unsigned nb = (unsigned)(nn * 8 + rfrag) * SW2_STRIDE + (unsigned)kt * 32 + (unsigned)tg * 8;
                uint2 bhv = *(const uint2*)(smem + OFF_W + nb);
                uint2 blv = *(const uint2*)(smem + OFF_WLO + nb);
                unsigned bh[2] = {bhv.x, bhv.y};
                unsigned bl[2] = {blv.x, blv.y};
                mma_bf16(acc2[0][nn], gh[0][kt], bh);
                mma_bf16(acc2[1][nn], gh[1][kt], bh);
                mma_bf16(acc2[0][nn], gl[0][kt], bh);
                mma_bf16(acc2[1][nn], gl[1][kt], bh);
                mma_bf16(acc2[0][nn], gh[0][kt], bl);
                mma_bf16(acc2[1][nn], gh[1][kt], bl);
            }
        }

        if (c == 0) {
            // residual: dst[b][oc][ta] = acc + b_res[oc] + src[oc][ta+d]
#pragma unroll
            for (int mt = 0; mt < 2; mt++) {
#pragma unroll
                for (int nn = 0; nn < 8; nn++) {
                    int oc = nn * 8 + 2 * tg;
#pragma unroll
                    for (int h = 0; h < 2; h++) {
                        int rr = w * 32 + mt * 16 + rfrag + 8 * h;
                        int ta = t0 + rr;
                        if (ta >= 0) {
                            float v0 = acc2[mt][nn][2 * h] + sBias[oc] + srcB[(size_t)oc * 8192 + ta + d];
                            float v1 = acc2[mt][nn][2 * h + 1] + sBias[oc + 1] + srcB[(size_t)(oc + 1) * 8192 + ta + d];
                            dst[(size_t)(b * 64 + oc) * 8192 + ta] = v0;
                            dst[(size_t)(b * 64 + oc + 1) * 8192 + ta] = v1;
                        }
                    }
                }
            }
        } else {
#pragma unroll
            for (int mt = 0; mt < 2; mt++) {
#pragma unroll
                for (int nn = 0; nn < 8; nn++) {
                    int cs = (c - 1) * 64 + nn * 8 + 2 * tg;
#pragma unroll
                    for (int h = 0; h < 2; h++) {
                        int rr = w * 32 + mt * 16 + rfrag + 8 * h;
                        int s = t0 + rr - skipOff;
                        if (s >= 0) {
                            float v0 = acc2[mt][nn][2 * h] + sBias[64 + cs];
                            float v1 = acc2[mt][nn][2 * h + 1] + sBias[64 + cs + 1];
                            skipOut[((size_t)b * 128 + cs) * 4096 + s] = v0;
                            skipOut[((size_t)b * 128 + cs + 1) * 4096 + s] = v1;
                        }
                    }
                }
            }
        }
    }
}

// ------------------------- launch -------------------------
extern "C" void kernel_launch(void* const* d_in, const int* in_sizes, int n_in,
                              void* d_out, int out_size) {
    const float* x      = (const float*)d_in[0];
    const float* w_dil  = (const float*)d_in[1];
    const float* w_res  = (const float*)d_in[2];
    const float* b_res  = (const float*)d_in[3];
    const float* w_skip = (const float*)d_in[4];
    const float* b_skip = (const float*)d_in[5];
    float* out = (float*)d_out;
    (void)in_sizes; (void)n_in; (void)out_size;

    cudaFuncSetAttribute(layer_kernel, cudaFuncAttributeMaxDynamicSharedMemorySize, SMEM_BYTES);

    float *bufA, *bufB, *biasP;
    unsigned char *w1P, *w2P;
    cudaGetSymbolAddress((void**)&bufA, g_buf0);
    cudaGetSymbolAddress((void**)&bufB, g_buf1);
    cudaGetSymbolAddress((void**)&w1P, g_w1img);
    cudaGetSymbolAddress((void**)&w2P, g_w2img);
    cudaGetSymbolAddress((void**)&biasP, g_bias);

    repack_kernel<<<(RNTOT + 255) / 256, 256>>>(w_dil, w_res, b_res, w_skip, b_skip);

    int T = 8192;
    const float* src = x;
    for (int l = 0; l < NLAYERS; l++) {
        int d = 1 << (l % 10);
        int L = T - d;
        float* dst = (l & 1) ? bufB : bufA;
        int nTiles = (L + TB - 1) / TB;
        dim3 grid(nTiles, 8);
        layer_kernel<<<grid, NT, SMEM_BYTES>>>(
            src, dst,
            w1P + (size_t)l * 36864, w2P + (size_t)l * 61440, biasP + (size_t)l * 192,
            out + (size_t)l * 8 * 128 * 4096, d, L, nTiles);
        src = dst;
        T = L;
    }
}

// round 13
// speedup vs baseline: 1.1250x; 1.1250x over previous
#include <cuda_runtime.h>
#include <cuda_bf16.h>
#include <math.h>

#define NLAYERS 40
#define TB 128
#define NT 256

// interleaved hi/lo images: each 16B slot = [hi 8B | lo 8B]
// strides % 128 == 32 -> conflict-free (minimum-phase) 16B fragment loads
#define SA_STRIDE 544      // A rows: 8 chunks x 64B + 32 pad
#define SW1_STRIDE 544     // W1 rows: same
#define SW2_STRIDE 288     // W2 rows: 4 chunks x 64B + 32 pad

// smem layout (bytes)
#define OFF_A    0                  // 128*544 = 69632
#define OFF_W    69632              // weight region: max(W1 34816, W2 chunk 18432)
#define OFF_BIAS 104448             // 192 f32
#define SMEM_BYTES 105216

#define W1_BYTES 34816              // 64*544
#define W2_CHUNK_BYTES 18432        // 64*288
#define W2_BYTES 55296              // 192*288

// ---------------- global scratch ----------------
__device__ float g_buf0[8 * 64 * 8192];
__device__ float g_buf1[8 * 64 * 8192];
__device__ __align__(16) unsigned char g_w1img[NLAYERS * W1_BYTES];
__device__ __align__(16) unsigned char g_w2img[NLAYERS * W2_BYTES];
__device__ float g_bias[NLAYERS * 192];

// ---------------- helpers ----------------
__device__ __forceinline__ void mma_bf16(float* c, const unsigned* a, const unsigned* b) {
    asm volatile(
        "mma.sync.aligned.m16n8k16.row.col.f32.bf16.bf16.f32 "
        "{%0,%1,%2,%3}, {%4,%5,%6,%7}, {%8,%9}, {%0,%1,%2,%3};"
        : "+f"(c[0]), "+f"(c[1]), "+f"(c[2]), "+f"(c[3])
        : "r"(a[0]), "r"(a[1]), "r"(a[2]), "r"(a[3]), "r"(b[0]), "r"(b[1]));
}

__device__ __forceinline__ void split2(float a, float b, unsigned& hi, unsigned& lo) {
    __nv_bfloat16 ha = __float2bfloat16(a), hb = __float2bfloat16(b);
    float la = a - __bfloat162float(ha);
    float lb = b - __bfloat162float(hb);
    hi = ((unsigned)__bfloat16_as_ushort(hb) << 16) | (unsigned)__bfloat16_as_ushort(ha);
    __nv_bfloat16 bla = __float2bfloat16(la), blb = __float2bfloat16(lb);
    lo = ((unsigned)__bfloat16_as_ushort(blb) << 16) | (unsigned)__bfloat16_as_ushort(bla);
}

__device__ __forceinline__ float gate_fn(float y) {
    float ay = fabsf(y);
    float e1 = __expf(-ay);
    float e2 = e1 * e1;
    float th = __fdividef(1.f - e2, 1.f + e2);
    float sp = __fdividef(1.f, 1.f + e1);
    float sig = (y >= 0.f) ? sp : (1.f - sp);
    return copysignf(th, y) * sig;
}

// element col (within row) -> byte offset of its HI bf16 inside the 64B chunk
// chunk holds 16 elements; tg slot t (0..3) = 16B [hi: e(2t),e(2t+1),e(2t+8),e(2t+9) | lo: same]
__device__ __forceinline__ unsigned ilv2(unsigned col) {
    unsigned eo = col & 15;
    unsigned w = eo >> 1;
    return (w & 3) * 16 + (w >> 2) * 4 + (col & 1) * 2;
}

// ------------------------- weight repack -------------------------
#define RN1 (NLAYERS * 64 * 64 * 2)
#define RN2 (NLAYERS * 64 * 64)
#define RN3 (NLAYERS * 128 * 64)
#define RN4 (NLAYERS * 64)
#define RN5 (NLAYERS * 128)
#define RNTOT (RN1 + RN2 + RN3 + RN4 + RN5)

__global__ void repack_kernel(const float* __restrict__ wd, const float* __restrict__ wr,
                              const float* __restrict__ br, const float* __restrict__ ws,
                              const float* __restrict__ bs) {
    int idx = blockIdx.x * blockDim.x + threadIdx.x;
    if (idx < RN1) {  // w_dil[l][o][i][k] -> W1 row o, col k*64+i
        float v = wd[idx];
        int k = idx & 1, i = (idx >> 1) & 63, o = (idx >> 7) & 63, l = idx >> 13;
        __nv_bfloat16 h = __float2bfloat16(v);
        __nv_bfloat16 lo = __float2bfloat16(v - __bfloat162float(h));
        unsigned col = (unsigned)(k * 64 + i);
        unsigned byte = (unsigned)o * SW1_STRIDE + (col >> 4) * 64 + ilv2(col);
        *(__nv_bfloat16*)(g_w1img + (size_t)l * W1_BYTES + byte) = h;
        *(__nv_bfloat16*)(g_w1img + (size_t)l * W1_BYTES + byte + 8) = lo;
        return;
    }
    idx -= RN1;
    if (idx < RN2) {  // w_res[l][o][i] -> W2 row o
        float v = wr[idx];
        int i = idx & 63, o = (idx >> 6) & 63, l = idx >> 12;
        __nv_bfloat16 h = __float2bfloat16(v);
        __nv_bfloat16 lo = __float2bfloat16(v - __bfloat162float(h));
        unsigned byte = (unsigned)o * SW2_STRIDE + ((unsigned)i >> 4) * 64 + ilv2((unsigned)i);
        *(__nv_bfloat16*)(g_w2img + (size_t)l * W2_BYTES + byte) = h;
        *(__nv_bfloat16*)(g_w2img + (size_t)l * W2_BYTES + byte + 8) = lo;
        return;
    }
    idx -= RN2;
    if (idx < RN3) {  // w_skip[l][o][i] -> W2 row 64+o
        float v = ws[idx];
        int i = idx & 63, o = (idx >> 6) & 127, l = idx >> 13;
        __nv_bfloat16 h = __float2bfloat16(v);
        __nv_bfloat16 lo = __float2bfloat16(v - __bfloat162float(h));
        unsigned byte = (unsigned)(64 + o) * SW2_STRIDE + ((unsigned)i >> 4) * 64 + ilv2((unsigned)i);
        *(__nv_bfloat16*)(g_w2img + (size_t)l * W2_BYTES + byte) = h;
        *(__nv_bfloat16*)(g_w2img + (size_t)l * W2_BYTES + byte + 8) = lo;
        return;
    }
    idx -= RN3;
    if (idx < RN4) { int o = idx & 63, l = idx >> 6; g_bias[l * 192 + o] = br[idx]; return; }
    idx -= RN4;
    if (idx < RN5) { int o = idx & 127, l = idx >> 7; g_bias[l * 192 + 64 + o] = bs[idx]; return; }
}

// ------------------------- fused mma.sync layer kernel -------------------------
// CTA: 128 timesteps x one batch. 8 warps; warp w owns rows 16w..16w+15.
__global__ __launch_bounds__(NT, 2) void layer_kernel(
    const float* __restrict__ src, float* __restrict__ dst,
    const unsigned char* __restrict__ w1img, const unsigned char* __restrict__ w2img,
    const float* __restrict__ bias, float* __restrict__ skipOut,
    int d, int L, int nTiles) {
    extern __shared__ unsigned char smem[];
    const int tid = threadIdx.x;
    const int lane = tid & 31;
    const int w = tid >> 5;
    const int b = blockIdx.y;
    const int t0 = L - (nTiles - blockIdx.x) * TB;
    const int Tin = L + d;

    // ---- stage W1 (2176 uint4) + bias ----
    {
        const uint4* g1 = (const uint4*)w1img;
        uint4* s1 = (uint4*)(smem + OFF_W);
#pragma unroll
        for (int k = 0; k < 9; k++) {
            int i = tid + NT * k;
            if (i < 2176) s1[i] = g1[i];
        }
        float* sBias = (float*)(smem + OFF_BIAS);
        if (tid < 192) sBias[tid] = bias[tid];
    }

    // ---- stage A: thread = (row, tap). Coalesced gmem loads, interleaved hi/lo scatter ----
    const float* srcB = src + (size_t)b * 64 * 8192;
    {
        const int row = tid & 127;
        const int tap = tid >> 7;
        const int sh = tap ? d : 0;
        int g = t0 + row + sh;
        g = min(max(g, 0), Tin - 1);
        const float* colp = srcB + g;
        unsigned rowb = (unsigned)row * SA_STRIDE;
#pragma unroll
        for (int cc = 0; cc < 4; cc++) {
            float v[16];
#pragma unroll
            for (int e = 0; e < 16; e++) v[e] = colp[(size_t)(cc * 16 + e) * 8192];
            unsigned addr0 = rowb + (unsigned)(tap * 4 + cc) * 64;
#pragma unroll
            for (int t = 0; t < 4; t++) {
                unsigned h0, l0, h1, l1;
                split2(v[2 * t], v[2 * t + 1], h0, l0);
                split2(v[2 * t + 8], v[2 * t + 9], h1, l1);
                *(uint4*)(smem + OFF_A + addr0 + t * 16) = make_uint4(h0, h1, l0, l1);
            }
        }
    }
    __syncthreads();

    const int tg = lane & 3;
    const int rfrag = lane >> 2;

    // ---------------- phase 1: y = A @ W1^T (3-split bf16) ----------------
    float acc[8][4];
#pragma unroll
    for (int nn = 0; nn < 8; nn++)
#pragma unroll
        for (int q = 0; q < 4; q++) acc[nn][q] = 0.f;

#pragma unroll 2
    for (int kk = 0; kk < 8; kk++) {
        unsigned ra = (unsigned)(w * 16 + rfrag) * SA_STRIDE + (unsigned)kk * 64 + (unsigned)tg * 16;
        uint4 u = *(const uint4*)(smem + OFF_A + ra);
        uint4 vv = *(const uint4*)(smem + OFF_A + ra + 8 * SA_STRIDE);
        unsigned ah[4] = {u.x, vv.x, u.y, vv.y};
        unsigned al[4] = {u.z, vv.z, u.w, vv.w};
#pragma unroll
        for (int nn = 0; nn < 8; nn++) {
            unsigned nb = (unsigned)(nn * 8 + rfrag) * SW1_STRIDE + (unsigned)kk * 64 + (unsigned)tg * 16;
            uint4 bb = *(const uint4*)(smem + OFF_W + nb);
            unsigned bh[2] = {bb.x, bb.y};
            unsigned bl[2] = {bb.z, bb.w};
            mma_bf16(acc[nn], ah, bh);
            mma_bf16(acc[nn], al, bh);
            mma_bf16(acc[nn], ah, bl);
        }
    }

    // ---------------- gate -> phase2 A fragments (registers only) ----------------
    unsigned gh[4][4], gl[4][4];
#pragma unroll
    for (int kt = 0; kt < 4; kt++) {
        int n0 = 2 * kt, n1 = 2 * kt + 1;
        split2(gate_fn(acc[n0][0]), gate_fn(acc[n0][1]), gh[kt][0], gl[kt][0]);
        split2(gate_fn(acc[n0][2]), gate_fn(acc[n0][3]), gh[kt][1], gl[kt][1]);
        split2(gate_fn(acc[n1][0]), gate_fn(acc[n1][1]), gh[kt][2], gl[kt][2]);
        split2(gate_fn(acc[n1][2]), gate_fn(acc[n1][3]), gh[kt][3], gl[kt][3]);
    }

    // ---------------- phase 2: [res | skip] = G @ W2^T, W2 staged per 64-ch chunk ----------------
    const int skipOff = L - 4096;
    const bool needSkip = (t0 + TB > skipOff);
    const int nch = needSkip ? 3 : 1;
    const float* sBias = (const float*)(smem + OFF_BIAS);

    for (int c = 0; c < nch; c++) {
        __syncthreads();   // everyone done reading the weight region
        {
            const uint4* gw = (const uint4*)(w2img + (size_t)c * W2_CHUNK_BYTES);
            uint4* sw = (uint4*)(smem + OFF_W);
            // 1152 uint4
#pragma unroll
            for (int k = 0; k < 5; k++) {
                int i = tid + NT * k;
                if (i < 1152) sw[i] = gw[i];
            }
        }
        __syncthreads();

        float acc2[8][4];
#pragma unroll
        for (int nn = 0; nn < 8; nn++)
#pragma unroll
            for (int q = 0; q < 4; q++) acc2[nn][q] = 0.f;

#pragma unroll
        for (int kt = 0; kt < 4; kt++) {
#pragma unroll
            for (int nn = 0; nn < 8; nn++) {
                unsigned nb = (unsigned)(nn * 8 + rfrag) * SW2_STRIDE + (unsigned)kt * 64 + (unsigned)tg * 16;
                uint4 bb = *(const uint4*)(smem + OFF_W + nb);
                unsigned bh[2] = {bb.x, bb.y};
                unsigned bl[2] = {bb.z, bb.w};
                mma_bf16(acc2[nn], gh[kt], bh);
                mma_bf16(acc2[nn], gl[kt], bh);
                mma_bf16(acc2[nn], gh[kt], bl);
            }
        }

        if (c == 0) {
            // residual: dst[b][oc][ta] = acc + b_res[oc] + src[oc][ta+d]
#pragma unroll
            for (int nn = 0; nn < 8; nn++) {
                int oc = nn * 8 + 2 * tg;
#pragma unroll
                for (int h = 0; h < 2; h++) {
                    int rr = w * 16 + rfrag + 8 * h;
                    int ta = t0 + rr;
                    if (ta >= 0) {
                        float v0 = acc2[nn][2 * h] + sBias[oc] + srcB[(size_t)oc * 8192 + ta + d];
                        float v1 = acc2[nn][2 * h + 1] + sBias[oc + 1] + srcB[(size_t)(oc + 1) * 8192 + ta + d];
                        dst[(size_t)(b * 64 + oc) * 8192 + ta] = v0;
                        dst[(size_t)(b * 64 + oc + 1) * 8192 + ta] = v1;
                    }
                }
            }
        } else {
#pragma unroll
            for (int nn = 0; nn < 8; nn++) {
                int cs = (c - 1) * 64 + nn * 8 + 2 * tg;
#pragma unroll
                for (int h = 0; h < 2; h++) {
                    int rr = w * 16 + rfrag + 8 * h;
                    int s = t0 + rr - skipOff;
                    if (s >= 0) {
                        float v0 = acc2[nn][2 * h] + sBias[64 + cs];
                        float v1 = acc2[nn][2 * h + 1] + sBias[64 + cs + 1];
                        skipOut[((size_t)b * 128 + cs) * 4096 + s] = v0;
                        skipOut[((size_t)b * 128 + cs + 1) * 4096 + s] = v1;
                    }
                }
            }
        }
    }
}

// ------------------------- launch -------------------------
extern "C" void kernel_launch(void* const* d_in, const int* in_sizes, int n_in,
                              void* d_out, int out_size) {
    const float* x      = (const float*)d_in[0];
    const float* w_dil  = (const float*)d_in[1];
    const float* w_res  = (const float*)d_in[2];
    const float* b_res  = (const float*)d_in[3];
    const float* w_skip = (const float*)d_in[4];
    const float* b_skip = (const float*)d_in[5];
    float* out = (float*)d_out;
    (void)in_sizes; (void)n_in; (void)out_size;

    cudaFuncSetAttribute(layer_kernel, cudaFuncAttributeMaxDynamicSharedMemorySize, SMEM_BYTES);

    float *bufA, *bufB, *biasP;
    unsigned char *w1P, *w2P;
    cudaGetSymbolAddress((void**)&bufA, g_buf0);
    cudaGetSymbolAddress((void**)&bufB, g_buf1);
    cudaGetSymbolAddress((void**)&w1P, g_w1img);
    cudaGetSymbolAddress((void**)&w2P, g_w2img);
    cudaGetSymbolAddress((void**)&biasP, g_bias);

    repack_kernel<<<(RNTOT + 255) / 256, 256>>>(w_dil, w_res, b_res, w_skip, b_skip);

    int T = 8192;
    const float* src = x;
    for (int l = 0; l < NLAYERS; l++) {
        int d = 1 << (l % 10);
        int L = T - d;
        float* dst = (l & 1) ? bufB : bufA;
        int nTiles = (L + TB - 1) / TB;
        dim3 grid(nTiles, 8);
        layer_kernel<<<grid, NT, SMEM_BYTES>>>(
            src, dst,
            w1P + (size_t)l * W1_BYTES, w2P + (size_t)l * W2_BYTES, biasP + (size_t)l * 192,
            out + (size_t)l * 8 * 128 * 4096, d, L, nTiles);
        src = dst;
        T = L;
    }
}

// round 14
// speedup vs baseline: 1.2789x; 1.1368x over previous
#include <cuda_runtime.h>
#include <cuda_bf16.h>
#include <math.h>

#define NLAYERS 40
#define TB 128
#define NT 256

// padded strides: stride(bytes) % 128 == 32 -> conflict-free 8B fragment loads
#define SA_STRIDE 288      // A rows: 256B data + 32 pad
#define SW1_STRIDE 288     // W1 rows: 256B data + 32 pad
#define SW2_STRIDE 160     // W2 rows: 128B data + 32 pad

// smem layout (bytes)
#define OFF_A_HI 0                  // 128*288 = 36864
#define OFF_A_LO 36864              // 36864
#define OFF_W    73728              // weight hi region (20480: W1-hi 18432 or 2 W2-chunk-hi 20480)
#define OFF_WLO  94208              // weight lo region (20480)
#define OFF_BIAS 114688             // 192 f32
#define SMEM_BYTES 115456

#define W1_BYTES 36864              // hi 18432 | lo 18432
#define W2_BYTES 61440              // hi 30720 | lo 30720 (192 rows * 160)

// ---------------- global scratch ----------------
__device__ float g_buf0[8 * 64 * 8192];
__device__ float g_buf1[8 * 64 * 8192];
__device__ __align__(16) unsigned char g_w1img[NLAYERS * W1_BYTES];
__device__ __align__(16) unsigned char g_w2img[NLAYERS * W2_BYTES];
__device__ float g_bias[NLAYERS * 192];

// ---------------- helpers ----------------
__device__ __forceinline__ void mma_bf16(float* c, const unsigned* a, const unsigned* b) {
    asm volatile(
        "mma.sync.aligned.m16n8k16.row.col.f32.bf16.bf16.f32 "
        "{%0,%1,%2,%3}, {%4,%5,%6,%7}, {%8,%9}, {%0,%1,%2,%3};"
        : "+f"(c[0]), "+f"(c[1]), "+f"(c[2]), "+f"(c[3])
        : "r"(a[0]), "r"(a[1]), "r"(a[2]), "r"(a[3]), "r"(b[0]), "r"(b[1]));
}

__device__ __forceinline__ void split2(float a, float b, unsigned& hi, unsigned& lo) {
    __nv_bfloat16 ha = __float2bfloat16(a), hb = __float2bfloat16(b);
    float la = a - __bfloat162float(ha);
    float lb = b - __bfloat162float(hb);
    hi = ((unsigned)__bfloat16_as_ushort(hb) << 16) | (unsigned)__bfloat16_as_ushort(ha);
    __nv_bfloat16 bla = __float2bfloat16(la), blb = __float2bfloat16(lb);
    lo = ((unsigned)__bfloat16_as_ushort(blb) << 16) | (unsigned)__bfloat16_as_ushort(bla);
}

__device__ __forceinline__ float gate_fn(float y) {
    float ay = fabsf(y);
    float e1 = __expf(-ay);
    float e2 = e1 * e1;
    float th = __fdividef(1.f - e2, 1.f + e2);
    float sp = __fdividef(1.f, 1.f + e1);
    float sig = (y >= 0.f) ? sp : (1.f - sp);
    return copysignf(th, y) * sig;
}

// word-pair interleave within a 32B K-chunk: element e (0..15, bf16) -> byte offset
__device__ __forceinline__ unsigned ilv(unsigned e) {
    unsigned w = e >> 1;
    unsigned nw = (w < 4) ? (w * 8) : ((w - 4) * 8 + 4);
    return nw + (e & 1) * 2;
}

// ------------------------- weight repack -------------------------
#define RN1 (NLAYERS * 64 * 64 * 2)
#define RN2 (NLAYERS * 64 * 64)
#define RN3 (NLAYERS * 128 * 64)
#define RN4 (NLAYERS * 64)
#define RN5 (NLAYERS * 128)
#define RNTOT (RN1 + RN2 + RN3 + RN4 + RN5)

__global__ void repack_kernel(const float* __restrict__ wd, const float* __restrict__ wr,
                              const float* __restrict__ br, const float* __restrict__ ws,
                              const float* __restrict__ bs) {
    int idx = blockIdx.x * blockDim.x + threadIdx.x;
    if (idx < RN1) {  // w_dil[l][o][i][k] -> W1 row o, col k*64+i
        float v = wd[idx];
        int k = idx & 1, i = (idx >> 1) & 63, o = (idx >> 7) & 63, l = idx >> 13;
        __nv_bfloat16 h = __float2bfloat16(v);
        __nv_bfloat16 lo = __float2bfloat16(v - __bfloat162float(h));
        unsigned col = (unsigned)(k * 64 + i);
        unsigned byte = (unsigned)o * SW1_STRIDE + (col >> 4) * 32 + ilv(col & 15);
        *(__nv_bfloat16*)(g_w1img + (size_t)l * W1_BYTES + byte) = h;
        *(__nv_bfloat16*)(g_w1img + (size_t)l * W1_BYTES + 18432 + byte) = lo;
        return;
    }
    idx -= RN1;
    if (idx < RN2) {  // w_res[l][o][i] -> W2 row o
        float v = wr[idx];
        int i = idx & 63, o = (idx >> 6) & 63, l = idx >> 12;
        __nv_bfloat16 h = __float2bfloat16(v);
        __nv_bfloat16 lo = __float2bfloat16(v - __bfloat162float(h));
        unsigned byte = (unsigned)o * SW2_STRIDE + ((unsigned)i >> 4) * 32 + ilv((unsigned)i & 15);
        *(__nv_bfloat16*)(g_w2img + (size_t)l * W2_BYTES + byte) = h;
        *(__nv_bfloat16*)(g_w2img + (size_t)l * W2_BYTES + 30720 + byte) = lo;
        return;
    }
    idx -= RN2;
    if (idx < RN3) {  // w_skip[l][o][i] -> W2 row 64+o
        float v = ws[idx];
        int i = idx & 63, o = (idx >> 6) & 127, l = idx >> 13;
        __nv_bfloat16 h = __float2bfloat16(v);
        __nv_bfloat16 lo = __float2bfloat16(v - __bfloat162float(h));
        unsigned byte = (unsigned)(64 + o) * SW2_STRIDE + ((unsigned)i >> 4) * 32 + ilv((unsigned)i & 15);
        *(__nv_bfloat16*)(g_w2img + (size_t)l * W2_BYTES + byte) = h;
        *(__nv_bfloat16*)(g_w2img + (size_t)l * W2_BYTES + 30720 + byte) = lo;
        return;
    }
    idx -= RN3;
    if (idx < RN4) { int o = idx & 63, l = idx >> 6; g_bias[l * 192 + o] = br[idx]; return; }
    idx -= RN4;
    if (idx < RN5) { int o = idx & 127, l = idx >> 7; g_bias[l * 192 + 64 + o] = bs[idx]; return; }
}

// ------------------------- fused mma.sync layer kernel -------------------------
// CTA: 128 timesteps x one batch. 8 warps; warp w owns rows 16w..16w+15.
__global__ __launch_bounds__(NT, 2) void layer_kernel(
    const float* __restrict__ src, float* __restrict__ dst,
    const unsigned char* __restrict__ w1img, const unsigned char* __restrict__ w2img,
    const float* __restrict__ bias, float* __restrict__ skipOut,
    int d, int L, int nTiles) {
    extern __shared__ unsigned char smem[];
    const int tid = threadIdx.x;
    const int lane = tid & 31;
    const int w = tid >> 5;
    const int b = blockIdx.y;
    const int t0 = L - (nTiles - blockIdx.x) * TB;
    const int Tin = L + d;

    // ---- stage W1 (hi 1152 u4, lo 1152 u4) + bias ----
    {
        const uint4* ghi = (const uint4*)w1img;
        const uint4* glo = (const uint4*)(w1img + 18432);
        uint4* shi = (uint4*)(smem + OFF_W);
        uint4* slo = (uint4*)(smem + OFF_WLO);
        for (int i = tid; i < 1152; i += NT) { shi[i] = ghi[i]; slo[i] = glo[i]; }
        float* sBias = (float*)(smem + OFF_BIAS);
        if (tid < 192) sBias[tid] = bias[tid];
    }

    // ---- stage A: thread = (row, tap). Coalesced gmem loads, bf16 hi/lo scatter ----
    const float* srcB = src + (size_t)b * 64 * 8192;
    {
        const int row = tid & 127;
        const int tap = tid >> 7;
        const int sh = tap ? d : 0;
        int g = t0 + row + sh;
        g = min(max(g, 0), Tin - 1);
        const float* colp = srcB + g;
        unsigned rowb = (unsigned)row * SA_STRIDE;
#pragma unroll
        for (int cc = 0; cc < 4; cc++) {
            float v[16];
#pragma unroll
            for (int e = 0; e < 16; e++) v[e] = colp[(size_t)(cc * 16 + e) * 8192];
            unsigned addr0 = rowb + (unsigned)(tap * 4 + cc) * 32;
#pragma unroll
            for (int hh = 0; hh < 2; hh++) {
                unsigned h[4], l[4];
                split2(v[4 * hh + 0], v[4 * hh + 1], h[0], l[0]);
                split2(v[4 * hh + 8], v[4 * hh + 9], h[1], l[1]);
                split2(v[4 * hh + 2], v[4 * hh + 3], h[2], l[2]);
                split2(v[4 * hh + 10], v[4 * hh + 11], h[3], l[3]);
                unsigned a = addr0 + hh * 16;
                *(uint4*)(smem + OFF_A_HI + a) = make_uint4(h[0], h[1], h[2], h[3]);
                *(uint4*)(smem + OFF_A_LO + a) = make_uint4(l[0], l[1], l[2], l[3]);
            }
        }
    }
    __syncthreads();

    const int tg = lane & 3;
    const int rfrag = lane >> 2;

    // ---------------- phase 1: y = A @ W1^T (3-split bf16) ----------------
    float acc[8][4];
#pragma unroll
    for (int nn = 0; nn < 8; nn++)
#pragma unroll
        for (int q = 0; q < 4; q++) acc[nn][q] = 0.f;

#pragma unroll 2
    for (int kk = 0; kk < 8; kk++) {
        unsigned ra = (unsigned)(w * 16 + rfrag) * SA_STRIDE + (unsigned)kk * 32 + (unsigned)tg * 8;
        uint2 uh = *(const uint2*)(smem + OFF_A_HI + ra);
        uint2 vh = *(const uint2*)(smem + OFF_A_HI + ra + 8 * SA_STRIDE);
        uint2 ul = *(const uint2*)(smem + OFF_A_LO + ra);
        uint2 vl = *(const uint2*)(smem + OFF_A_LO + ra + 8 * SA_STRIDE);
        unsigned ah[4] = {uh.x, vh.x, uh.y, vh.y};
        unsigned al[4] = {ul.x, vl.x, ul.y, vl.y};
#pragma unroll
        for (int nn = 0; nn < 8; nn++) {
            unsigned nb = (unsigned)(nn * 8 + rfrag) * SW1_STRIDE + (unsigned)kk * 32 + (unsigned)tg * 8;
            uint2 bhv = *(const uint2*)(smem + OFF_W + nb);
            uint2 blv = *(const uint2*)(smem + OFF_WLO + nb);
            unsigned bh[2] = {bhv.x, bhv.y};
            unsigned bl[2] = {blv.x, blv.y};
            mma_bf16(acc[nn], ah, bh);
            mma_bf16(acc[nn], al, bh);
            mma_bf16(acc[nn], ah, bl);
        }
    }

    // ---------------- gate -> phase2 A fragments (registers only) ----------------
    unsigned gh[4][4], gl[4][4];
#pragma unroll
    for (int kt = 0; kt < 4; kt++) {
        int n0 = 2 * kt, n1 = 2 * kt + 1;
        split2(gate_fn(acc[n0][0]), gate_fn(acc[n0][1]), gh[kt][0], gl[kt][0]);
        split2(gate_fn(acc[n0][2]), gate_fn(acc[n0][3]), gh[kt][1], gl[kt][1]);
        split2(gate_fn(acc[n1][0]), gate_fn(acc[n1][1]), gh[kt][2], gl[kt][2]);
        split2(gate_fn(acc[n1][2]), gate_fn(acc[n1][3]), gh[kt][3], gl[kt][3]);
    }

    // ---------------- phase 2: [res | skip] = G @ W2^T ----------------
    const int skipOff = L - 4096;
    const bool needSkip = (t0 + TB > skipOff);
    const int nch = needSkip ? 3 : 1;
    const float* sBias = (const float*)(smem + OFF_BIAS);
    const uint4* w2hi = (const uint4*)w2img;
    const uint4* w2lo = (const uint4*)(w2img + 30720);
    uint4* shi = (uint4*)(smem + OFF_W);
    uint4* slo = (uint4*)(smem + OFF_WLO);

    for (int c = 0; c < nch; c++) {
        if (c == 0) {
            __syncthreads();   // done reading W1
            int nu4 = needSkip ? 1280 : 640;    // chunks 0 (+1)
            for (int i = tid; i < nu4; i += NT) { shi[i] = w2hi[i]; slo[i] = w2lo[i]; }
            __syncthreads();
        } else if (c == 2) {
            __syncthreads();   // done reading chunks 0/1
            for (int i = tid; i < 640; i += NT) { shi[i] = w2hi[1280 + i]; slo[i] = w2lo[1280 + i]; }
            __syncthreads();
        }
        const unsigned wb = OFF_W + ((c == 1) ? 10240u : 0u);
        const unsigned wlb = OFF_WLO + ((c == 1) ? 10240u : 0u);

        float acc2[8][4];
#pragma unroll
        for (int nn = 0; nn < 8; nn++)
#pragma unroll
            for (int q = 0; q < 4; q++) acc2[nn][q] = 0.f;

#pragma unroll
        for (int kt = 0; kt < 4; kt++) {
#pragma unroll
            for (int nn = 0; nn < 8; nn++) {
                unsigned nb = (unsigned)(nn * 8 + rfrag) * SW2_STRIDE + (unsigned)kt * 32 + (unsigned)tg * 8;
                uint2 bhv = *(const uint2*)(smem + wb + nb);
                uint2 blv = *(const uint2*)(smem + wlb + nb);
                unsigned bh[2] = {bhv.x, bhv.y};
                unsigned bl[2] = {blv.x, blv.y};
                mma_bf16(acc2[nn], gh[kt], bh);
                mma_bf16(acc2[nn], gl[kt], bh);
                mma_bf16(acc2[nn], gh[kt], bl);
            }
        }

        if (c == 0) {
            // residual: dst[b][oc][ta] = acc + b_res[oc] + x_tap1 (reconstructed from A smem)
#pragma unroll
            for (int nn = 0; nn < 8; nn++) {
                int oc = nn * 8 + 2 * tg;
                unsigned q = ((unsigned)oc & 15) >> 1;
                unsigned colOff = (4u + ((unsigned)oc >> 4)) * 32 + (q & 3) * 8 + (q >> 2) * 4;
#pragma unroll
                for (int h = 0; h < 2; h++) {
                    int rr = w * 16 + rfrag + 8 * h;
                    int ta = t0 + rr;
                    if (ta >= 0) {
                        unsigned off = (unsigned)rr * SA_STRIDE + colOff;
                        unsigned xh = *(const unsigned*)(smem + OFF_A_HI + off);
                        unsigned xl = *(const unsigned*)(smem + OFF_A_LO + off);
                        float x0 = __uint_as_float(xh << 16) + __uint_as_float(xl << 16);
                        float x1 = __uint_as_float(xh & 0xffff0000u) + __uint_as_float(xl & 0xffff0000u);
                        float v0 = acc2[nn][2 * h] + sBias[oc] + x0;
                        float v1 = acc2[nn][2 * h + 1] + sBias[oc + 1] + x1;
                        dst[(size_t)(b * 64 + oc) * 8192 + ta] = v0;
                        dst[(size_t)(b * 64 + oc + 1) * 8192 + ta] = v1;
                    }
                }
            }
        } else {
#pragma unroll
            for (int nn = 0; nn < 8; nn++) {
                int cs = (c - 1) * 64 + nn * 8 + 2 * tg;
#pragma unroll
                for (int h = 0; h < 2; h++) {
                    int rr = w * 16 + rfrag + 8 * h;
                    int s = t0 + rr - skipOff;
                    if (s >= 0) {
                        float v0 = acc2[nn][2 * h] + sBias[64 + cs];
                        float v1 = acc2[nn][2 * h + 1] + sBias[64 + cs + 1];
                        skipOut[((size_t)b * 128 + cs) * 4096 + s] = v0;
                        skipOut[((size_t)b * 128 + cs + 1) * 4096 + s] = v1;
                    }
                }
            }
        }
    }
}

// ------------------------- launch -------------------------
extern "C" void kernel_launch(void* const* d_in, const int* in_sizes, int n_in,
                              void* d_out, int out_size) {
    const float* x      = (const float*)d_in[0];
    const float* w_dil  = (const float*)d_in[1];
    const float* w_res  = (const float*)d_in[2];
    const float* b_res  = (const float*)d_in[3];
    const float* w_skip = (const float*)d_in[4];
    const float* b_skip = (const float*)d_in[5];
    float* out = (float*)d_out;
    (void)in_sizes; (void)n_in; (void)out_size;

    cudaFuncSetAttribute(layer_kernel, cudaFuncAttributeMaxDynamicSharedMemorySize, SMEM_BYTES);

    float *bufA, *bufB, *biasP;
    unsigned char *w1P, *w2P;
    cudaGetSymbolAddress((void**)&bufA, g_buf0);
    cudaGetSymbolAddress((void**)&bufB, g_buf1);
    cudaGetSymbolAddress((void**)&w1P, g_w1img);
    cudaGetSymbolAddress((void**)&w2P, g_w2img);
    cudaGetSymbolAddress((void**)&biasP, g_bias);

    repack_kernel<<<(RNTOT + 255) / 256, 256>>>(w_dil, w_res, b_res, w_skip, b_skip);

    int T = 8192;
    const float* src = x;
    for (int l = 0; l < NLAYERS; l++) {
        int d = 1 << (l % 10);
        int L = T - d;
        float* dst = (l & 1) ? bufB : bufA;
        int nTiles = (L + TB - 1) / TB;
        dim3 grid(nTiles, 8);
        layer_kernel<<<grid, NT, SMEM_BYTES>>>(
            src, dst,
            w1P + (size_t)l * W1_BYTES, w2P + (size_t)l * W2_BYTES, biasP + (size_t)l * 192,
            out + (size_t)l * 8 * 128 * 4096, d, L, nTiles);
        src = dst;
        T = L;
    }
}